// round 2
// baseline (speedup 1.0000x reference)
#include <cuda_runtime.h>
#include <math.h>

// Problem constants
// B=16, C=512, NH=8, DK=64, H=W=32, N=H*W=1024

// ---------------------------------------------------------------------------
// Device scratch (allocation-free rule: __device__ globals)
// q,k,v stored d-major: [b][h][d][n]  (n contiguous)
// att stored [b][c][n] with c = h*64 + d (matches the reference's head-outer
// channel order feeding w_o)
// lh/lw: [b][h][n][64] (r = 0..62 valid, slot 63 unused padding)
// ---------------------------------------------------------------------------
__device__ float g_q  [16 * 8 * 64 * 1024];
__device__ float g_k  [16 * 8 * 64 * 1024];
__device__ float g_v  [16 * 8 * 64 * 1024];
__device__ float g_att[16 * 512 * 1024];
__device__ float g_lh [16 * 8 * 1024 * 64];
__device__ float g_lw [16 * 8 * 1024 * 64];

// ---------------------------------------------------------------------------
// SGEMM: out(512 x 1024) = A(512x512) @ X_b(512x1024) per batch.
// BM=BN=128, BK=16, 256 threads, 8x8 micro-tile, float4 smem paths.
// MODE 0: scatter into d-major qkv layout  out[((b*8+h)*64+d)*1024+n], h=o&7, d=o>>3
// MODE 1: plain [b][o][n] + bias (final output projection)
// ---------------------------------------------------------------------------
template <int MODE>
__global__ __launch_bounds__(256)
void gemm512_kernel(const float* __restrict__ A, const float* __restrict__ X,
                    float* __restrict__ out, const float* __restrict__ bias)
{
    const int b  = blockIdx.z;
    const int bm = blockIdx.y * 128;
    const int bn = blockIdx.x * 128;
    const float* __restrict__ Xb = X + b * 512 * 1024;

    __shared__ float As[16][132];   // [c][o], padded: 2-way max on store, bcast-free read
    __shared__ float Bs[16][128];   // [c][n]

    const int tid = threadIdx.x;
    const int tr  = tid >> 4;       // 0..15 -> rows tr*8
    const int tc  = tid & 15;       // 0..15 -> cols tc*8

    float acc[8][8];
#pragma unroll
    for (int i = 0; i < 8; i++)
#pragma unroll
        for (int j = 0; j < 8; j++) acc[i][j] = 0.f;

    for (int k0 = 0; k0 < 512; k0 += 16) {
        // A tile 128x16, transpose into smem
#pragma unroll
        for (int l = 0; l < 2; l++) {
            int flat = tid + l * 256;          // float4 id 0..511
            int row  = flat >> 2;              // 0..127 (o)
            int c4   = (flat & 3) * 4;         // 0,4,8,12 (c)
            float4 av = *reinterpret_cast<const float4*>(&A[(bm + row) * 512 + k0 + c4]);
            As[c4 + 0][row] = av.x;
            As[c4 + 1][row] = av.y;
            As[c4 + 2][row] = av.z;
            As[c4 + 3][row] = av.w;
        }
        // B tile 16x128, direct
#pragma unroll
        for (int l = 0; l < 2; l++) {
            int flat = tid + l * 256;
            int row  = flat >> 5;              // 0..15 (c)
            int col  = (flat & 31) * 4;        // 0..124 (n)
            *reinterpret_cast<float4*>(&Bs[row][col]) =
                *reinterpret_cast<const float4*>(&Xb[(k0 + row) * 1024 + bn + col]);
        }
        __syncthreads();

#pragma unroll
        for (int kk = 0; kk < 16; kk++) {
            float a[8], bb[8];
            *reinterpret_cast<float4*>(&a[0]) = *reinterpret_cast<float4*>(&As[kk][tr * 8]);
            *reinterpret_cast<float4*>(&a[4]) = *reinterpret_cast<float4*>(&As[kk][tr * 8 + 4]);
            *reinterpret_cast<float4*>(&bb[0]) = *reinterpret_cast<float4*>(&Bs[kk][tc * 8]);
            *reinterpret_cast<float4*>(&bb[4]) = *reinterpret_cast<float4*>(&Bs[kk][tc * 8 + 4]);
#pragma unroll
            for (int i = 0; i < 8; i++)
#pragma unroll
                for (int j = 0; j < 8; j++)
                    acc[i][j] += a[i] * bb[j];
        }
        __syncthreads();
    }

    if (MODE == 0) {
        // d-major scatter: 8 consecutive o = one d, all 8 heads -> per-(i) the
        // half-warp writes 128 consecutive n floats: coalesced.
#pragma unroll
        for (int i = 0; i < 8; i++) {
            int o = bm + tr * 8 + i;
            int h = o & 7, d = o >> 3;
            float* dst = out + (((b * 8 + h) * 64 + d) * 1024 + bn + tc * 8);
#pragma unroll
            for (int j = 0; j < 8; j++) dst[j] = acc[i][j];
        }
    } else {
#pragma unroll
        for (int i = 0; i < 8; i++) {
            int o = bm + tr * 8 + i;
            float bo = bias[o];
            float* dst = out + ((b * 512 + o) * 1024 + bn + tc * 8);
#pragma unroll
            for (int j = 0; j < 8; j++) dst[j] = acc[i][j] + bo;
        }
    }
}

// ---------------------------------------------------------------------------
// Per-query rel-pos tables: lh[n][r] = sum_d q[n][d]*rel_h[r][d] (r<63), same lw.
// One block = one (b,h) x 64-query chunk. 256 threads: i = tid%64, r-group = tid/64.
// ---------------------------------------------------------------------------
__global__ __launch_bounds__(256)
void bias_tables_kernel(const float* __restrict__ q,
                        const float* __restrict__ rel_h, const float* __restrict__ rel_w,
                        float* __restrict__ lh, float* __restrict__ lw)
{
    const int blk = blockIdx.x;          // 0..2047
    const int bh  = blk >> 4;            // 0..127
    const int n0  = (blk & 15) * 64;
    const float* __restrict__ qb = q + bh * 64 * 1024;   // [d][n]

    __shared__ float Qs[64][65];         // [i][d], conflict-free both directions
    __shared__ float Rh[63][64];
    __shared__ float Rw[63][64];

    const int tid = threadIdx.x;

#pragma unroll
    for (int l = 0; l < 16; l++) {       // 4096 scalar elems
        int flat = tid + l * 256;
        int d = flat >> 6, i = flat & 63;
        Qs[i][d] = qb[d * 1024 + n0 + i];
    }
#pragma unroll
    for (int l = 0; l < 16; l++) {
        int flat = tid + l * 256;
        if (flat < 63 * 64) {
            (&Rh[0][0])[flat] = rel_h[flat];
            (&Rw[0][0])[flat] = rel_w[flat];
        }
    }
    __syncthreads();

    const int i  = tid & 63;
    const int r0 = (tid >> 6) * 16;      // 0,16,32,48

    float acch[16], accw[16];
#pragma unroll
    for (int t = 0; t < 16; t++) { acch[t] = 0.f; accw[t] = 0.f; }

    for (int d = 0; d < 64; d++) {
        float qv = Qs[i][d];
#pragma unroll
        for (int t = 0; t < 16; t++) {
            int r = r0 + t;
            if (r < 63) {
                acch[t] += qv * Rh[r][d];
                accw[t] += qv * Rw[r][d];
            }
        }
    }

    const int base = (bh * 1024 + n0 + i) * 64;
#pragma unroll
    for (int t = 0; t < 16; t++) {
        int r = r0 + t;
        if (r < 63) {
            lh[base + r] = acch[t];
            lw[base + r] = accw[t];
        }
    }
}

// ---------------------------------------------------------------------------
// Flash attention with content-aware rel-pos bias.
// Per block: one (b,h), one 64-query tile. 128 threads (ty=tid/16 rows ty*8,
// tx=tid%15 cols tx*4). Online softmax over 16 key tiles of 64.
// s = (q.k + lh[i_k - x + 31] + lw[j_k - y + 31]) / 8
// Output staged through smem so global writes are coalesced rows of att[c][n].
// ---------------------------------------------------------------------------
struct AttnSmem {
    float Qs[64][65];   // [i][d]
    float Ks[64][68];   // [d][j]  (float4 along j)
    float Vs[64][65];   // [j][d]
    float Ps[64][68];   // [r][j]  (float4 writes along j)
    float Lh[64][64];   // [i][r]
    float Lw[64][64];
};

__global__ __launch_bounds__(128)
void attn_kernel(const float* __restrict__ q, const float* __restrict__ k,
                 const float* __restrict__ v,
                 const float* __restrict__ lh, const float* __restrict__ lw,
                 float* __restrict__ att)
{
    extern __shared__ unsigned char smem_raw[];
    AttnSmem& sm = *reinterpret_cast<AttnSmem*>(smem_raw);

    const int bh = blockIdx.y;           // 0..127
    const int b  = bh >> 3, h = bh & 7;
    const int q0 = blockIdx.x * 64;

    const float* __restrict__ qb = q + bh * 64 * 1024;
    const float* __restrict__ kb = k + bh * 64 * 1024;
    const float* __restrict__ vb = v + bh * 64 * 1024;

    const int tid = threadIdx.x;         // 128
    const int ty  = tid >> 4;            // 0..7 -> rows ty*8
    const int tx  = tid & 15;            // 0..15 -> cols tx*4

    // Load Q (transposed to [i][d]) and bias tables
#pragma unroll
    for (int l = 0; l < 32; l++) {
        int flat = tid + l * 128;
        int d = flat >> 6, i = flat & 63;
        sm.Qs[i][d] = qb[d * 1024 + q0 + i];
    }
#pragma unroll
    for (int l = 0; l < 32; l++) {
        int flat = tid + l * 128;
        int i = flat >> 6, r = flat & 63;
        int gidx = (bh * 1024 + q0 + i) * 64 + r;
        sm.Lh[i][r] = lh[gidx];
        sm.Lw[i][r] = lw[gidx];
    }

    float m[8], lsum[8], o[8][4];
#pragma unroll
    for (int rr = 0; rr < 8; rr++) {
        m[rr] = -1e30f; lsum[rr] = 0.f;
#pragma unroll
        for (int cc = 0; cc < 4; cc++) o[rr][cc] = 0.f;
    }

    int xr[8], yr[8];
#pragma unroll
    for (int rr = 0; rr < 8; rr++) {
        int nq = q0 + ty * 8 + rr;
        xr[rr] = nq >> 5;
        yr[rr] = nq & 31;
    }

    __syncthreads();

    for (int kt = 0; kt < 16; kt++) {
        // K tile [d][j]: natural layout, float4
#pragma unroll
        for (int l = 0; l < 8; l++) {
            int flat = tid + l * 128;    // float4 id 0..1023
            int d = flat >> 4, j4 = (flat & 15) * 4;
            *reinterpret_cast<float4*>(&sm.Ks[d][j4]) =
                *reinterpret_cast<const float4*>(&kb[d * 1024 + kt * 64 + j4]);
        }
        // V tile transposed to [j][d] (scalar, conflict-free via 65-pad)
#pragma unroll
        for (int l = 0; l < 32; l++) {
            int flat = tid + l * 128;
            int d = flat >> 6, j = flat & 63;
            sm.Vs[j][d] = vb[d * 1024 + kt * 64 + j];
        }
        __syncthreads();

        // S = Q @ K^T  (8x4 per thread)
        float s[8][4];
#pragma unroll
        for (int rr = 0; rr < 8; rr++)
#pragma unroll
            for (int cc = 0; cc < 4; cc++) s[rr][cc] = 0.f;

#pragma unroll 8
        for (int kk = 0; kk < 64; kk++) {
            float a[8];
#pragma unroll
            for (int rr = 0; rr < 8; rr++) a[rr] = sm.Qs[ty * 8 + rr][kk];
            float4 bv = *reinterpret_cast<float4*>(&sm.Ks[kk][tx * 4]);
#pragma unroll
            for (int rr = 0; rr < 8; rr++) {
                s[rr][0] += a[rr] * bv.x;
                s[rr][1] += a[rr] * bv.y;
                s[rr][2] += a[rr] * bv.z;
                s[rr][3] += a[rr] * bv.w;
            }
        }

        // bias + scale + online softmax
        const int kt2 = kt * 2;
#pragma unroll
        for (int rr = 0; rr < 8; rr++) {
            int row = ty * 8 + rr;
#pragma unroll
            for (int cc = 0; cc < 4; cc++) {
                int jj = tx * 4 + cc;
                float bias = sm.Lh[row][kt2 + (jj >> 5) - xr[rr] + 31]
                           + sm.Lw[row][(jj & 31) - yr[rr] + 31];
                s[rr][cc] = (s[rr][cc] + bias) * 0.125f;
            }
            float mloc = fmaxf(fmaxf(s[rr][0], s[rr][1]), fmaxf(s[rr][2], s[rr][3]));
#pragma unroll
            for (int off = 8; off >= 1; off >>= 1)
                mloc = fmaxf(mloc, __shfl_xor_sync(0xffffffffu, mloc, off));
            float mnew  = fmaxf(m[rr], mloc);
            float alpha = __expf(m[rr] - mnew);
            m[rr] = mnew;
            float rsum = 0.f;
#pragma unroll
            for (int cc = 0; cc < 4; cc++) {
                s[rr][cc] = __expf(s[rr][cc] - mnew);
                rsum += s[rr][cc];
            }
#pragma unroll
            for (int off = 8; off >= 1; off >>= 1)
                rsum += __shfl_xor_sync(0xffffffffu, rsum, off);
            lsum[rr] = lsum[rr] * alpha + rsum;
#pragma unroll
            for (int cc = 0; cc < 4; cc++) o[rr][cc] *= alpha;
            // stage P
            *reinterpret_cast<float4*>(&sm.Ps[row][tx * 4]) =
                make_float4(s[rr][0], s[rr][1], s[rr][2], s[rr][3]);
        }
        __syncthreads();

        // O += P @ V
#pragma unroll 8
        for (int jj = 0; jj < 64; jj++) {
            float a[8];
#pragma unroll
            for (int rr = 0; rr < 8; rr++) a[rr] = sm.Ps[ty * 8 + rr][jj];
            float bv[4];
#pragma unroll
            for (int cc = 0; cc < 4; cc++) bv[cc] = sm.Vs[jj][tx * 4 + cc];
#pragma unroll
            for (int rr = 0; rr < 8; rr++)
#pragma unroll
                for (int cc = 0; cc < 4; cc++)
                    o[rr][cc] += a[rr] * bv[cc];
        }
        __syncthreads();
    }

    // normalize + stage transposed to [d][i] (reuse Ks), then coalesced store
#pragma unroll
    for (int rr = 0; rr < 8; rr++) {
        float inv = 1.0f / lsum[rr];
#pragma unroll
        for (int cc = 0; cc < 4; cc++)
            sm.Ks[tx * 4 + cc][ty * 8 + rr] = o[rr][cc] * inv;
    }
    __syncthreads();

    float* ab = att + (b * 512 + h * 64) * 1024 + q0;
#pragma unroll
    for (int l = 0; l < 32; l++) {
        int flat = tid + l * 128;
        int d = flat >> 6, i = flat & 63;
        ab[d * 1024 + i] = sm.Ks[d][i];
    }
}

// ---------------------------------------------------------------------------
// Launch
// ---------------------------------------------------------------------------
extern "C" void kernel_launch(void* const* d_in, const int* in_sizes, int n_in,
                              void* d_out, int out_size)
{
    const float* x     = (const float*)d_in[0];
    const float* w_q   = (const float*)d_in[1];
    const float* w_k   = (const float*)d_in[2];
    const float* w_v   = (const float*)d_in[3];
    const float* w_o   = (const float*)d_in[4];
    const float* b_o   = (const float*)d_in[5];
    const float* rel_h = (const float*)d_in[6];
    const float* rel_w = (const float*)d_in[7];
    float* out = (float*)d_out;

    float *pq, *pk, *pv, *patt, *plh, *plw;
    cudaGetSymbolAddress((void**)&pq,   g_q);
    cudaGetSymbolAddress((void**)&pk,   g_k);
    cudaGetSymbolAddress((void**)&pv,   g_v);
    cudaGetSymbolAddress((void**)&patt, g_att);
    cudaGetSymbolAddress((void**)&plh,  g_lh);
    cudaGetSymbolAddress((void**)&plw,  g_lw);

    cudaFuncSetAttribute(attn_kernel, cudaFuncAttributeMaxDynamicSharedMemorySize,
                         (int)sizeof(AttnSmem));

    dim3 gp(8, 4, 16);   // n-tiles, m-tiles, batch
    gemm512_kernel<0><<<gp, 256>>>(w_q, x, pq, nullptr);
    gemm512_kernel<0><<<gp, 256>>>(w_k, x, pk, nullptr);
    gemm512_kernel<0><<<gp, 256>>>(w_v, x, pv, nullptr);

    bias_tables_kernel<<<2048, 256>>>(pq, rel_h, rel_w, plh, plw);

    attn_kernel<<<dim3(16, 128), 128, sizeof(AttnSmem)>>>(pq, pk, pv, plh, plw, patt);

    gemm512_kernel<1><<<gp, 256>>>(w_o, patt, out, b_o);
}